// round 1
// baseline (speedup 1.0000x reference)
#include <cuda_runtime.h>
#include <math.h>

// Problem dims (fixed by the dataset)
#define BB 16
#define SS 1024
#define HH 512
#define CC 7
#define MM (BB * SS)        // 16384 rows
#define H3 (3 * HH)         // 1536
#define EPSV 1e-10f

// ----------------------------------------------------------------------------
// Static scratch (global memory; no allocations anywhere)
// ----------------------------------------------------------------------------
__device__ float g_total[MM * HH];          // text+audio+visual
__device__ float g_T[MM * HH];              // total @ (0.5*Wc_seg)
__device__ float g_G[3 * MM * HH];          // feat_m @ Aw
__device__ float g_h0[MM * H3];             // gated concat features
__device__ float g_nadj[BB * SS * SS];      // normalized adjacency
__device__ float g_tmp[MM * HH];            // h @ W
__device__ float g_h[MM * HH];              // relu(adj @ tmp + b)
__device__ float g_ent[3 * MM];
__device__ float g_dsi[BB * SS];
__device__ float g_Aw[HH * HH];
__device__ float g_Wh[HH * HH];
__device__ float g_wlast[HH];
__device__ float g_WcT[CC * HH];

// ----------------------------------------------------------------------------
// Weight prep:  Aw = W[0:H]+W[H:2H]-0.5*W[2H:3H] ; Wh = 0.5*W[2H:3H] ; wlast
// ----------------------------------------------------------------------------
__global__ void prep_weights(const float* __restrict__ gW) {
    int idx = blockIdx.x * blockDim.x + threadIdx.x;
    if (idx < HH * HH) {
        float wa = gW[idx];
        float wb = gW[HH * HH + idx];
        float wc = gW[2 * HH * HH + idx];
        g_Aw[idx] = wa + wb - 0.5f * wc;
        g_Wh[idx] = 0.5f * wc;
    }
    if (idx < HH) g_wlast[idx] = gW[3 * HH * HH + idx];
}

__global__ void transpose_wc(const float* __restrict__ Wc) {
    int idx = blockIdx.x * blockDim.x + threadIdx.x;   // over H*C
    if (idx < HH * CC) {
        int k = idx / CC, c = idx % CC;
        g_WcT[c * HH + k] = Wc[k * CC + c];
    }
}

// ----------------------------------------------------------------------------
// total = text + audio + visual   (vectorized)
// ----------------------------------------------------------------------------
__global__ void sum3_kernel(const float4* __restrict__ a, const float4* __restrict__ b,
                            const float4* __restrict__ c, float4* __restrict__ o, int n4) {
    for (int i = blockIdx.x * blockDim.x + threadIdx.x; i < n4; i += gridDim.x * blockDim.x) {
        float4 x = a[i], y = b[i], z = c[i];
        o[i] = make_float4(x.x + y.x + z.x, x.y + y.y + z.y,
                           x.z + y.z + z.z, x.w + y.w + z.w);
    }
}

// ----------------------------------------------------------------------------
// Entropy: block per (row, modality). 128 threads x float4 covers H=512.
// ----------------------------------------------------------------------------
__global__ void entropy_kernel(const float* __restrict__ text,
                               const float* __restrict__ audio,
                               const float* __restrict__ visual) {
    __shared__ float sh[4];
    const float* f = (blockIdx.y == 0) ? text : (blockIdx.y == 1) ? audio : visual;
    long long r = blockIdx.x;
    float4 v = *(const float4*)(f + r * HH + threadIdx.x * 4);
    float ax = fabsf(v.x), ay = fabsf(v.y), az = fabsf(v.z), aw = fabsf(v.w);
    float s = ax + ay + az + aw;
    // warp reduce
    #pragma unroll
    for (int o = 16; o; o >>= 1) s += __shfl_down_sync(0xffffffffu, s, o);
    int lane = threadIdx.x & 31, w = threadIdx.x >> 5;
    if (lane == 0) sh[w] = s;
    __syncthreads();
    float total = sh[0] + sh[1] + sh[2] + sh[3];
    float inv = 1.0f / (total + EPSV);
    float f0 = ax * inv, f1 = ay * inv, f2 = az * inv, f3 = aw * inv;
    float e = f0 * logf(f0 + EPSV) + f1 * logf(f1 + EPSV)
            + f2 * logf(f2 + EPSV) + f3 * logf(f3 + EPSV);
    #pragma unroll
    for (int o = 16; o; o >>= 1) e += __shfl_down_sync(0xffffffffu, e, o);
    __syncthreads();
    if (lane == 0) sh[w] = e;
    __syncthreads();
    if (threadIdx.x == 0)
        g_ent[(long long)blockIdx.y * MM + r] = -(sh[0] + sh[1] + sh[2] + sh[3]);
}

// ----------------------------------------------------------------------------
// SGEMM: C = A[M,K] @ B[K,N] (+bias, relu).  64x64x16 tile, 4x4 microtile.
// Requires M%64==0, N%64==0, K%16==0 (true for all call sites).
// ----------------------------------------------------------------------------
template <int EPI>   // 0 = none, 1 = bias+relu
__global__ void __launch_bounds__(256) sgemm_kernel(
    const float* __restrict__ Ag, const float* __restrict__ Bg,
    const float* __restrict__ bias, float* __restrict__ Cg,
    int M, int N, int K, long long sA, long long sB, long long sC)
{
    __shared__ float As[16][64];
    __shared__ float Bs[16][64];
    const float* A = Ag + (long long)blockIdx.z * sA;
    const float* B = Bg + (long long)blockIdx.z * sB;
    float*       C = Cg + (long long)blockIdx.z * sC;
    int t = threadIdx.x;
    int block_row = blockIdx.y * 64;
    int block_col = blockIdx.x * 64;
    int arow = t >> 2, acol = (t & 3) * 4;      // A tile: 64 rows x 16 k
    int brow = t >> 4, bcol = (t & 15) * 4;     // B tile: 16 k x 64 cols
    int tx = t & 15, ty = t >> 4;
    float acc[4][4] = {};

    for (int k0 = 0; k0 < K; k0 += 16) {
        float4 av = *(const float4*)(A + (long long)(block_row + arow) * K + k0 + acol);
        As[acol + 0][arow] = av.x;
        As[acol + 1][arow] = av.y;
        As[acol + 2][arow] = av.z;
        As[acol + 3][arow] = av.w;
        float4 bv = *(const float4*)(B + (long long)(k0 + brow) * N + block_col + bcol);
        *(float4*)&Bs[brow][bcol] = bv;
        __syncthreads();
        #pragma unroll
        for (int k = 0; k < 16; k++) {
            float4 aq = *(const float4*)&As[k][ty * 4];
            float4 bq = *(const float4*)&Bs[k][tx * 4];
            acc[0][0] += aq.x * bq.x; acc[0][1] += aq.x * bq.y;
            acc[0][2] += aq.x * bq.z; acc[0][3] += aq.x * bq.w;
            acc[1][0] += aq.y * bq.x; acc[1][1] += aq.y * bq.y;
            acc[1][2] += aq.y * bq.z; acc[1][3] += aq.y * bq.w;
            acc[2][0] += aq.z * bq.x; acc[2][1] += aq.z * bq.y;
            acc[2][2] += aq.z * bq.z; acc[2][3] += aq.z * bq.w;
            acc[3][0] += aq.w * bq.x; acc[3][1] += aq.w * bq.y;
            acc[3][2] += aq.w * bq.z; acc[3][3] += aq.w * bq.w;
        }
        __syncthreads();
    }

    int col = block_col + tx * 4;
    #pragma unroll
    for (int i = 0; i < 4; i++) {
        int row = block_row + ty * 4 + i;
        float4 v = make_float4(acc[i][0], acc[i][1], acc[i][2], acc[i][3]);
        if (EPI == 1) {
            float4 bb = *(const float4*)(bias + col);
            v.x = fmaxf(v.x + bb.x, 0.0f);
            v.y = fmaxf(v.y + bb.y, 0.0f);
            v.z = fmaxf(v.z + bb.z, 0.0f);
            v.w = fmaxf(v.w + bb.w, 0.0f);
        }
        *(float4*)(C + (long long)row * N + col) = v;
    }
}

// ----------------------------------------------------------------------------
// gate_fuse: h0[r, m*H+j] = sigmoid(G_m + T + ent_m*wlast + gate_b) * feat_m
// ----------------------------------------------------------------------------
__global__ void gate_fuse_kernel(const float* __restrict__ gate_b,
                                 const float* __restrict__ text,
                                 const float* __restrict__ audio,
                                 const float* __restrict__ visual) {
    long long r = blockIdx.x;
    int m = blockIdx.y;
    const float* feat = (m == 0) ? text : (m == 1) ? audio : visual;
    float e = g_ent[(long long)m * MM + r];
    int j = threadIdx.x * 4;
    float4 gv = *(const float4*)(g_G + ((long long)m * MM + r) * HH + j);
    float4 tv = *(const float4*)(g_T + r * HH + j);
    float4 wv = *(const float4*)(g_wlast + j);
    float4 bv = *(const float4*)(gate_b + j);
    float4 fv = *(const float4*)(feat + r * HH + j);
    float4 o;
    float zx = gv.x + tv.x + e * wv.x + bv.x;
    float zy = gv.y + tv.y + e * wv.y + bv.y;
    float zz = gv.z + tv.z + e * wv.z + bv.z;
    float zw = gv.w + tv.w + e * wv.w + bv.w;
    o.x = fv.x / (1.0f + expf(-zx));
    o.y = fv.y / (1.0f + expf(-zy));
    o.z = fv.z / (1.0f + expf(-zz));
    o.w = fv.w / (1.0f + expf(-zw));
    *(float4*)(g_h0 + r * H3 + m * HH + j) = o;
}

// ----------------------------------------------------------------------------
// Degree + inverse sqrt: dsi[b,i] = 1/sqrt(1 + 0.5*sum_j(sp+tp) + eps)
// ----------------------------------------------------------------------------
__global__ void degree_kernel(const float* __restrict__ sp, const float* __restrict__ tp) {
    __shared__ float sh[8];
    long long b = blockIdx.y, i = blockIdx.x;
    const float* rs = sp + (b * SS + i) * SS;
    const float* rt = tp + (b * SS + i) * SS;
    float s = 0.0f;
    for (int j = threadIdx.x; j < SS; j += 256) s += rs[j] + rt[j];
    #pragma unroll
    for (int o = 16; o; o >>= 1) s += __shfl_down_sync(0xffffffffu, s, o);
    int lane = threadIdx.x & 31, w = threadIdx.x >> 5;
    if (lane == 0) sh[w] = s;
    __syncthreads();
    if (threadIdx.x == 0) {
        float D = 1.0f + 0.5f * (sh[0] + sh[1] + sh[2] + sh[3] + sh[4] + sh[5] + sh[6] + sh[7]);
        g_dsi[b * SS + i] = 1.0f / sqrtf(D + EPSV);
    }
}

__global__ void normadj_kernel(const float* __restrict__ sp, const float* __restrict__ tp) {
    long long n4 = (long long)BB * SS * SS / 4;
    for (long long g = (long long)blockIdx.x * blockDim.x + threadIdx.x; g < n4;
         g += (long long)gridDim.x * blockDim.x) {
        long long e = g * 4;
        int b = (int)(e / ((long long)SS * SS));
        long long rrem = e % ((long long)SS * SS);
        int i = (int)(rrem / SS);
        int j = (int)(rrem % SS);
        float4 a = *(const float4*)(sp + e);
        float4 c = *(const float4*)(tp + e);
        float di = g_dsi[(long long)b * SS + i];
        const float* dj = g_dsi + (long long)b * SS + j;
        float4 o;
        o.x = (0.5f * (a.x + c.x) + (j + 0 == i ? 1.0f : 0.0f)) * di * dj[0];
        o.y = (0.5f * (a.y + c.y) + (j + 1 == i ? 1.0f : 0.0f)) * di * dj[1];
        o.z = (0.5f * (a.z + c.z) + (j + 2 == i ? 1.0f : 0.0f)) * di * dj[2];
        o.w = (0.5f * (a.w + c.w) + (j + 3 == i ? 1.0f : 0.0f)) * di * dj[3];
        *(float4*)(g_nadj + e) = o;
    }
}

// ----------------------------------------------------------------------------
// Classifier: out[r,c] = h[r,:] . WcT[c,:] + bc[c].  Warp per class, block per row.
// ----------------------------------------------------------------------------
__global__ void classifier_kernel(const float* __restrict__ bc, float* __restrict__ out) {
    __shared__ float sh[HH];
    long long r = blockIdx.x;
    for (int k = threadIdx.x; k < HH; k += 224) sh[k] = g_h[r * HH + k];
    __syncthreads();
    int w = threadIdx.x >> 5, lane = threadIdx.x & 31;
    if (w < CC) {
        const float* wrow = g_WcT + w * HH;
        float s = 0.0f;
        #pragma unroll
        for (int k = lane; k < HH; k += 32) s += sh[k] * wrow[k];
        #pragma unroll
        for (int o = 16; o; o >>= 1) s += __shfl_down_sync(0xffffffffu, s, o);
        if (lane == 0) out[r * CC + w] = s + bc[w];
    }
}

// ----------------------------------------------------------------------------
// Launch
// ----------------------------------------------------------------------------
extern "C" void kernel_launch(void* const* d_in, const int* in_sizes, int n_in,
                              void* d_out, int out_size) {
    const float* text   = (const float*)d_in[0];
    const float* audio  = (const float*)d_in[1];
    const float* visual = (const float*)d_in[2];
    const float* sp     = (const float*)d_in[3];
    const float* tp     = (const float*)d_in[4];
    // d_in[5] = qmask (unused by reference)
    const float* gate_W = (const float*)d_in[6];
    const float* gate_b = (const float*)d_in[7];
    const float* W0 = (const float*)d_in[8];
    const float* b0 = (const float*)d_in[9];
    const float* W1 = (const float*)d_in[10];
    const float* b1 = (const float*)d_in[11];
    const float* W2 = (const float*)d_in[12];
    const float* b2 = (const float*)d_in[13];
    const float* Wc = (const float*)d_in[14];
    const float* bc = (const float*)d_in[15];
    float* out = (float*)d_out;

    float *pTotal, *pT, *pG, *pH0, *pNadj, *pTmp, *pH;
    cudaGetSymbolAddress((void**)&pTotal, g_total);
    cudaGetSymbolAddress((void**)&pT,     g_T);
    cudaGetSymbolAddress((void**)&pG,     g_G);
    cudaGetSymbolAddress((void**)&pH0,    g_h0);
    cudaGetSymbolAddress((void**)&pNadj,  g_nadj);
    cudaGetSymbolAddress((void**)&pTmp,   g_tmp);
    cudaGetSymbolAddress((void**)&pH,     g_h);
    float *pAw, *pWh;
    cudaGetSymbolAddress((void**)&pAw, g_Aw);
    cudaGetSymbolAddress((void**)&pWh, g_Wh);

    // 1) weight prep
    prep_weights<<<(HH * HH + 255) / 256, 256>>>(gate_W);
    transpose_wc<<<(HH * CC + 255) / 256, 256>>>(Wc);

    // 2) total = text+audio+visual
    int n4 = MM * HH / 4;
    sum3_kernel<<<4096, 256>>>((const float4*)text, (const float4*)audio,
                               (const float4*)visual, (float4*)pTotal, n4);

    // 3) entropy (speaker path)
    entropy_kernel<<<dim3(MM, 3), 128>>>(text, audio, visual);

    // 4) gating GEMMs: G_m = feat_m @ Aw ; T = total @ Wh
    dim3 gemm_grid(HH / 64, MM / 64, 1);
    sgemm_kernel<0><<<gemm_grid, 256>>>(text,   pAw, nullptr, pG,               MM, HH, HH, 0, 0, 0);
    sgemm_kernel<0><<<gemm_grid, 256>>>(audio,  pAw, nullptr, pG + (long long)MM * HH,     MM, HH, HH, 0, 0, 0);
    sgemm_kernel<0><<<gemm_grid, 256>>>(visual, pAw, nullptr, pG + 2LL * MM * HH, MM, HH, HH, 0, 0, 0);
    sgemm_kernel<0><<<gemm_grid, 256>>>(pTotal, pWh, nullptr, pT,               MM, HH, HH, 0, 0, 0);

    // 5) gate + fuse into h0 [M, 3H]
    gate_fuse_kernel<<<dim3(MM, 3), 128>>>(gate_b, text, audio, visual);

    // 6) normalized adjacency
    degree_kernel<<<dim3(SS, BB), 256>>>(sp, tp);
    normadj_kernel<<<8192, 256>>>(sp, tp);

    // 7) spectral GNN
    dim3 adj_grid(HH / 64, SS / 64, BB);
    long long sAdj = (long long)SS * SS, sF = (long long)SS * HH;

    sgemm_kernel<0><<<gemm_grid, 256>>>(pH0, W0, nullptr, pTmp, MM, HH, H3, 0, 0, 0);
    sgemm_kernel<1><<<adj_grid, 256>>>(pNadj, pTmp, b0, pH, SS, HH, SS, sAdj, sF, sF);

    sgemm_kernel<0><<<gemm_grid, 256>>>(pH, W1, nullptr, pTmp, MM, HH, HH, 0, 0, 0);
    sgemm_kernel<1><<<adj_grid, 256>>>(pNadj, pTmp, b1, pH, SS, HH, SS, sAdj, sF, sF);

    sgemm_kernel<0><<<gemm_grid, 256>>>(pH, W2, nullptr, pTmp, MM, HH, HH, 0, 0, 0);
    sgemm_kernel<1><<<adj_grid, 256>>>(pNadj, pTmp, b2, pH, SS, HH, SS, sAdj, sF, sF);

    // 8) classifier
    classifier_kernel<<<MM, 224>>>(bc, out);
}

// round 3
// speedup vs baseline: 2.7001x; 2.7001x over previous
#include <cuda_runtime.h>
#include <cuda_bf16.h>
#include <cstdint>
#include <math.h>

// Problem dims (fixed by the dataset)
#define BB 16
#define SS 1024
#define HH 512
#define CC 7
#define MM (BB * SS)        // 16384 rows
#define H3 (3 * HH)         // 1536
#define EPSV 1e-10f

// GEMM tiling
#define BM 128
#define BN 128
#define BK 32
#define LDA 40              // halves, padded (80B row stride -> conflict-free ldmatrix)
#define LDB 136             // halves, padded (272B row stride -> conflict-free ldmatrix)

// ----------------------------------------------------------------------------
// Static scratch (global memory; no allocations anywhere)
// ----------------------------------------------------------------------------
__device__ float g_total[MM * HH];          // text+audio+visual
__device__ float g_T[MM * HH];              // total @ (0.5*Wc_seg)
__device__ float g_G[3 * MM * HH];          // feat_m @ Aw
__device__ float g_h0[MM * H3];             // gated concat features
__device__ float g_nadj[BB * SS * SS];      // normalized adjacency
__device__ float g_tmp[MM * HH];            // h @ W
__device__ float g_h[MM * HH];              // relu(adj @ tmp + b)
__device__ float g_ent[3 * MM];
__device__ float g_dsi[BB * SS];
__device__ float g_Aw[HH * HH];
__device__ float g_Wh[HH * HH];
__device__ float g_wlast[HH];
__device__ float g_WcT[CC * HH];

// ----------------------------------------------------------------------------
// Weight prep:  Aw = W[0:H]+W[H:2H]-0.5*W[2H:3H] ; Wh = 0.5*W[2H:3H] ; wlast
// ----------------------------------------------------------------------------
__global__ void prep_weights(const float* __restrict__ gW) {
    int idx = blockIdx.x * blockDim.x + threadIdx.x;
    if (idx < HH * HH) {
        float wa = gW[idx];
        float wb = gW[HH * HH + idx];
        float wc = gW[2 * HH * HH + idx];
        g_Aw[idx] = wa + wb - 0.5f * wc;
        g_Wh[idx] = 0.5f * wc;
    }
    if (idx < HH) g_wlast[idx] = gW[3 * HH * HH + idx];
}

__global__ void transpose_wc(const float* __restrict__ Wc) {
    int idx = blockIdx.x * blockDim.x + threadIdx.x;   // over H*C
    if (idx < HH * CC) {
        int k = idx / CC, c = idx % CC;
        g_WcT[c * HH + k] = Wc[k * CC + c];
    }
}

// ----------------------------------------------------------------------------
// total = text + audio + visual   (vectorized)
// ----------------------------------------------------------------------------
__global__ void sum3_kernel(const float4* __restrict__ a, const float4* __restrict__ b,
                            const float4* __restrict__ c, float4* __restrict__ o, int n4) {
    for (int i = blockIdx.x * blockDim.x + threadIdx.x; i < n4; i += gridDim.x * blockDim.x) {
        float4 x = a[i], y = b[i], z = c[i];
        o[i] = make_float4(x.x + y.x + z.x, x.y + y.y + z.y,
                           x.z + y.z + z.z, x.w + y.w + z.w);
    }
}

// ----------------------------------------------------------------------------
// Entropy: block per (row, modality). 128 threads x float4 covers H=512.
// ----------------------------------------------------------------------------
__global__ void entropy_kernel(const float* __restrict__ text,
                               const float* __restrict__ audio,
                               const float* __restrict__ visual) {
    __shared__ float sh[4];
    const float* f = (blockIdx.y == 0) ? text : (blockIdx.y == 1) ? audio : visual;
    long long r = blockIdx.x;
    float4 v = *(const float4*)(f + r * HH + threadIdx.x * 4);
    float ax = fabsf(v.x), ay = fabsf(v.y), az = fabsf(v.z), aw = fabsf(v.w);
    float s = ax + ay + az + aw;
    #pragma unroll
    for (int o = 16; o; o >>= 1) s += __shfl_down_sync(0xffffffffu, s, o);
    int lane = threadIdx.x & 31, w = threadIdx.x >> 5;
    if (lane == 0) sh[w] = s;
    __syncthreads();
    float total = sh[0] + sh[1] + sh[2] + sh[3];
    float inv = 1.0f / (total + EPSV);
    float f0 = ax * inv, f1 = ay * inv, f2 = az * inv, f3 = aw * inv;
    float e = f0 * logf(f0 + EPSV) + f1 * logf(f1 + EPSV)
            + f2 * logf(f2 + EPSV) + f3 * logf(f3 + EPSV);
    #pragma unroll
    for (int o = 16; o; o >>= 1) e += __shfl_down_sync(0xffffffffu, e, o);
    __syncthreads();
    if (lane == 0) sh[w] = e;
    __syncthreads();
    if (threadIdx.x == 0)
        g_ent[(long long)blockIdx.y * MM + r] = -(sh[0] + sh[1] + sh[2] + sh[3]);
}

// ----------------------------------------------------------------------------
// bf16-split tensor-core GEMM: C = A[M,K] @ B[K,N] (+bias+relu).
// fp32 emulated as hi+lo bf16 (3 MMAs): err ~2^-16. Requires M%128, N%128, K%32 == 0.
// ----------------------------------------------------------------------------
__device__ __forceinline__ unsigned s2u(const void* p) {
    return (unsigned)__cvta_generic_to_shared(p);
}

#define MMA16816(d, a, b)                                                  \
    asm volatile(                                                          \
        "mma.sync.aligned.m16n8k16.row.col.f32.bf16.bf16.f32 "             \
        "{%0,%1,%2,%3}, {%4,%5,%6,%7}, {%8,%9}, {%0,%1,%2,%3};\n"          \
        : "+f"(d[0]), "+f"(d[1]), "+f"(d[2]), "+f"(d[3])                   \
        : "r"(a[0]), "r"(a[1]), "r"(a[2]), "r"(a[3]), "r"(b[0]), "r"(b[1]))

#define LDSM_X4(r0, r1, r2, r3, addr)                                      \
    asm volatile("ldmatrix.sync.aligned.m8n8.x4.shared.b16 "               \
                 "{%0,%1,%2,%3}, [%4];\n"                                  \
                 : "=r"(r0), "=r"(r1), "=r"(r2), "=r"(r3) : "r"(addr))

#define LDSM_X4T(r0, r1, r2, r3, addr)                                     \
    asm volatile("ldmatrix.sync.aligned.m8n8.x4.trans.shared.b16 "         \
                 "{%0,%1,%2,%3}, [%4];\n"                                  \
                 : "=r"(r0), "=r"(r1), "=r"(r2), "=r"(r3) : "r"(addr))

template <int EPI>   // 0 = none, 1 = bias+relu
__global__ void __launch_bounds__(256) mma_gemm(
    const float* __restrict__ Ag, const float* __restrict__ Bg,
    const float* __restrict__ bias, float* __restrict__ Cg,
    int M, int N, int K, long long sA, long long sB, long long sC)
{
    __shared__ __nv_bfloat16 Ah[BM * LDA];
    __shared__ __nv_bfloat16 Al[BM * LDA];
    __shared__ __nv_bfloat16 Bh[BK * LDB];
    __shared__ __nv_bfloat16 Bl[BK * LDB];

    const float* A = Ag + (long long)blockIdx.z * sA;
    const float* B = Bg + (long long)blockIdx.z * sB;
    float*       C = Cg + (long long)blockIdx.z * sC;

    int t = threadIdx.x, lane = t & 31, wid = t >> 5;
    int warp_m = wid >> 2, warp_n = wid & 3;    // 2 x 4 warps
    int brow = blockIdx.y * BM, bcol = blockIdx.x * BN;

    float acc[4][4][4];
    #pragma unroll
    for (int i = 0; i < 4; i++)
        #pragma unroll
        for (int j = 0; j < 4; j++)
            #pragma unroll
            for (int q = 0; q < 4; q++) acc[i][j][q] = 0.0f;

    for (int k0 = 0; k0 < K; k0 += BK) {
        // ---- A tile: 128 x 32 fp32 -> hi/lo bf16 smem ----
        #pragma unroll
        for (int i = 0; i < 4; i++) {
            int q = t + i * 256;               // float4 index, 1024 total
            int r = q >> 3, c = (q & 7) << 2;  // 8 float4 per row
            float4 v = *(const float4*)(A + (long long)(brow + r) * K + k0 + c);
            __nv_bfloat16 hx = __float2bfloat16(v.x);
            __nv_bfloat16 hy = __float2bfloat16(v.y);
            __nv_bfloat16 hz = __float2bfloat16(v.z);
            __nv_bfloat16 hw = __float2bfloat16(v.w);
            __nv_bfloat16 lx = __float2bfloat16(v.x - __bfloat162float(hx));
            __nv_bfloat16 ly = __float2bfloat16(v.y - __bfloat162float(hy));
            __nv_bfloat16 lz = __float2bfloat16(v.z - __bfloat162float(hz));
            __nv_bfloat16 lw = __float2bfloat16(v.w - __bfloat162float(hw));
            __nv_bfloat162* ph = (__nv_bfloat162*)&Ah[r * LDA + c];
            __nv_bfloat162* pl = (__nv_bfloat162*)&Al[r * LDA + c];
            ph[0] = __nv_bfloat162(hx, hy); ph[1] = __nv_bfloat162(hz, hw);
            pl[0] = __nv_bfloat162(lx, ly); pl[1] = __nv_bfloat162(lz, lw);
        }
        // ---- B tile: 32 x 128 fp32 -> hi/lo bf16 smem ----
        #pragma unroll
        for (int i = 0; i < 4; i++) {
            int q = t + i * 256;
            int r = q >> 5, c = (q & 31) << 2;  // 32 float4 per row
            float4 v = *(const float4*)(B + (long long)(k0 + r) * N + bcol + c);
            __nv_bfloat16 hx = __float2bfloat16(v.x);
            __nv_bfloat16 hy = __float2bfloat16(v.y);
            __nv_bfloat16 hz = __float2bfloat16(v.z);
            __nv_bfloat16 hw = __float2bfloat16(v.w);
            __nv_bfloat16 lx = __float2bfloat16(v.x - __bfloat162float(hx));
            __nv_bfloat16 ly = __float2bfloat16(v.y - __bfloat162float(hy));
            __nv_bfloat16 lz = __float2bfloat16(v.z - __bfloat162float(hz));
            __nv_bfloat16 lw = __float2bfloat16(v.w - __bfloat162float(hw));
            __nv_bfloat162* ph = (__nv_bfloat162*)&Bh[r * LDB + c];
            __nv_bfloat162* pl = (__nv_bfloat162*)&Bl[r * LDB + c];
            ph[0] = __nv_bfloat162(hx, hy); ph[1] = __nv_bfloat162(hz, hw);
            pl[0] = __nv_bfloat162(lx, ly); pl[1] = __nv_bfloat162(lz, lw);
        }
        __syncthreads();

        #pragma unroll
        for (int kk = 0; kk < BK; kk += 16) {
            unsigned ah[4][4], al[4][4], bh[4][2], bl[4][2];
            int arow = warp_m * 64 + (lane & 15);
            int acol = kk + ((lane >> 4) << 3);
            #pragma unroll
            for (int tm = 0; tm < 4; tm++) {
                const __nv_bfloat16* pa = &Ah[(arow + tm * 16) * LDA + acol];
                LDSM_X4(ah[tm][0], ah[tm][1], ah[tm][2], ah[tm][3], s2u(pa));
                const __nv_bfloat16* pb = &Al[(arow + tm * 16) * LDA + acol];
                LDSM_X4(al[tm][0], al[tm][1], al[tm][2], al[tm][3], s2u(pb));
            }
            int brow_ = kk + (lane & 15);
            #pragma unroll
            for (int tp = 0; tp < 2; tp++) {
                int bc = warp_n * 32 + tp * 16 + ((lane >> 4) << 3);
                const __nv_bfloat16* pb = &Bh[brow_ * LDB + bc];
                LDSM_X4T(bh[2 * tp][0], bh[2 * tp][1],
                         bh[2 * tp + 1][0], bh[2 * tp + 1][1], s2u(pb));
                const __nv_bfloat16* pl = &Bl[brow_ * LDB + bc];
                LDSM_X4T(bl[2 * tp][0], bl[2 * tp][1],
                         bl[2 * tp + 1][0], bl[2 * tp + 1][1], s2u(pl));
            }
            #pragma unroll
            for (int tm = 0; tm < 4; tm++)
                #pragma unroll
                for (int tn = 0; tn < 4; tn++) {
                    MMA16816(acc[tm][tn], ah[tm], bh[tn]);
                    MMA16816(acc[tm][tn], ah[tm], bl[tn]);
                    MMA16816(acc[tm][tn], al[tm], bh[tn]);
                }
        }
        __syncthreads();
    }

    // ---- epilogue ----
    int g = lane >> 2, tig = lane & 3;
    #pragma unroll
    for (int tm = 0; tm < 4; tm++)
        #pragma unroll
        for (int tn = 0; tn < 4; tn++) {
            int row = brow + warp_m * 64 + tm * 16 + g;
            int col = bcol + warp_n * 32 + tn * 8 + tig * 2;
            float2 v0 = make_float2(acc[tm][tn][0], acc[tm][tn][1]);
            float2 v1 = make_float2(acc[tm][tn][2], acc[tm][tn][3]);
            if (EPI == 1) {
                float b0 = bias[col], b1 = bias[col + 1];
                v0.x = fmaxf(v0.x + b0, 0.0f); v0.y = fmaxf(v0.y + b1, 0.0f);
                v1.x = fmaxf(v1.x + b0, 0.0f); v1.y = fmaxf(v1.y + b1, 0.0f);
            }
            *(float2*)(C + (long long)row * N + col) = v0;
            *(float2*)(C + (long long)(row + 8) * N + col) = v1;
        }
}

// ----------------------------------------------------------------------------
// gate_fuse: h0[r, m*H+j] = sigmoid(G_m + T + ent_m*wlast + gate_b) * feat_m
// ----------------------------------------------------------------------------
__global__ void gate_fuse_kernel(const float* __restrict__ gate_b,
                                 const float* __restrict__ text,
                                 const float* __restrict__ audio,
                                 const float* __restrict__ visual) {
    long long r = blockIdx.x;
    int m = blockIdx.y;
    const float* feat = (m == 0) ? text : (m == 1) ? audio : visual;
    float e = g_ent[(long long)m * MM + r];
    int j = threadIdx.x * 4;
    float4 gv = *(const float4*)(g_G + ((long long)m * MM + r) * HH + j);
    float4 tv = *(const float4*)(g_T + r * HH + j);
    float4 wv = *(const float4*)(g_wlast + j);
    float4 bv = *(const float4*)(gate_b + j);
    float4 fv = *(const float4*)(feat + r * HH + j);
    float4 o;
    float zx = gv.x + tv.x + e * wv.x + bv.x;
    float zy = gv.y + tv.y + e * wv.y + bv.y;
    float zz = gv.z + tv.z + e * wv.z + bv.z;
    float zw = gv.w + tv.w + e * wv.w + bv.w;
    o.x = fv.x / (1.0f + expf(-zx));
    o.y = fv.y / (1.0f + expf(-zy));
    o.z = fv.z / (1.0f + expf(-zz));
    o.w = fv.w / (1.0f + expf(-zw));
    *(float4*)(g_h0 + r * H3 + m * HH + j) = o;
}

// ----------------------------------------------------------------------------
// Degree + inverse sqrt: dsi[b,i] = 1/sqrt(1 + 0.5*sum_j(sp+tp) + eps)
// ----------------------------------------------------------------------------
__global__ void degree_kernel(const float* __restrict__ sp, const float* __restrict__ tp) {
    __shared__ float sh[8];
    long long b = blockIdx.y, i = blockIdx.x;
    const float* rs = sp + (b * SS + i) * SS;
    const float* rt = tp + (b * SS + i) * SS;
    float s = 0.0f;
    for (int j = threadIdx.x; j < SS; j += 256) s += rs[j] + rt[j];
    #pragma unroll
    for (int o = 16; o; o >>= 1) s += __shfl_down_sync(0xffffffffu, s, o);
    int lane = threadIdx.x & 31, w = threadIdx.x >> 5;
    if (lane == 0) sh[w] = s;
    __syncthreads();
    if (threadIdx.x == 0) {
        float D = 1.0f + 0.5f * (sh[0] + sh[1] + sh[2] + sh[3] + sh[4] + sh[5] + sh[6] + sh[7]);
        g_dsi[b * SS + i] = 1.0f / sqrtf(D + EPSV);
    }
}

__global__ void normadj_kernel(const float* __restrict__ sp, const float* __restrict__ tp) {
    long long n4 = (long long)BB * SS * SS / 4;
    for (long long g = (long long)blockIdx.x * blockDim.x + threadIdx.x; g < n4;
         g += (long long)gridDim.x * blockDim.x) {
        long long e = g * 4;
        int b = (int)(e / ((long long)SS * SS));
        long long rrem = e % ((long long)SS * SS);
        int i = (int)(rrem / SS);
        int j = (int)(rrem % SS);
        float4 a = *(const float4*)(sp + e);
        float4 c = *(const float4*)(tp + e);
        float di = g_dsi[(long long)b * SS + i];
        const float* dj = g_dsi + (long long)b * SS + j;
        float4 o;
        o.x = (0.5f * (a.x + c.x) + (j + 0 == i ? 1.0f : 0.0f)) * di * dj[0];
        o.y = (0.5f * (a.y + c.y) + (j + 1 == i ? 1.0f : 0.0f)) * di * dj[1];
        o.z = (0.5f * (a.z + c.z) + (j + 2 == i ? 1.0f : 0.0f)) * di * dj[2];
        o.w = (0.5f * (a.w + c.w) + (j + 3 == i ? 1.0f : 0.0f)) * di * dj[3];
        *(float4*)(g_nadj + e) = o;
    }
}

// ----------------------------------------------------------------------------
// Classifier: out[r,c] = h[r,:] . WcT[c,:] + bc[c].  Warp per class, block per row.
// ----------------------------------------------------------------------------
__global__ void classifier_kernel(const float* __restrict__ bc, float* __restrict__ out) {
    __shared__ float sh[HH];
    long long r = blockIdx.x;
    for (int k = threadIdx.x; k < HH; k += 224) sh[k] = g_h[r * HH + k];
    __syncthreads();
    int w = threadIdx.x >> 5, lane = threadIdx.x & 31;
    if (w < CC) {
        const float* wrow = g_WcT + w * HH;
        float s = 0.0f;
        #pragma unroll
        for (int k = lane; k < HH; k += 32) s += sh[k] * wrow[k];
        #pragma unroll
        for (int o = 16; o; o >>= 1) s += __shfl_down_sync(0xffffffffu, s, o);
        if (lane == 0) out[r * CC + w] = s + bc[w];
    }
}

// ----------------------------------------------------------------------------
// Launch
// ----------------------------------------------------------------------------
extern "C" void kernel_launch(void* const* d_in, const int* in_sizes, int n_in,
                              void* d_out, int out_size) {
    const float* text   = (const float*)d_in[0];
    const float* audio  = (const float*)d_in[1];
    const float* visual = (const float*)d_in[2];
    const float* sp     = (const float*)d_in[3];
    const float* tp     = (const float*)d_in[4];
    // d_in[5] = qmask (unused by reference)
    const float* gate_W = (const float*)d_in[6];
    const float* gate_b = (const float*)d_in[7];
    const float* W0 = (const float*)d_in[8];
    const float* b0 = (const float*)d_in[9];
    const float* W1 = (const float*)d_in[10];
    const float* b1 = (const float*)d_in[11];
    const float* W2 = (const float*)d_in[12];
    const float* b2 = (const float*)d_in[13];
    const float* Wc = (const float*)d_in[14];
    const float* bc = (const float*)d_in[15];
    float* out = (float*)d_out;

    float *pTotal, *pT, *pG, *pH0, *pNadj, *pTmp, *pH, *pAw, *pWh;
    cudaGetSymbolAddress((void**)&pTotal, g_total);
    cudaGetSymbolAddress((void**)&pT,     g_T);
    cudaGetSymbolAddress((void**)&pG,     g_G);
    cudaGetSymbolAddress((void**)&pH0,    g_h0);
    cudaGetSymbolAddress((void**)&pNadj,  g_nadj);
    cudaGetSymbolAddress((void**)&pTmp,   g_tmp);
    cudaGetSymbolAddress((void**)&pH,     g_h);
    cudaGetSymbolAddress((void**)&pAw,    g_Aw);
    cudaGetSymbolAddress((void**)&pWh,    g_Wh);

    // 1) weight prep
    prep_weights<<<(HH * HH + 255) / 256, 256>>>(gate_W);
    transpose_wc<<<(HH * CC + 255) / 256, 256>>>(Wc);

    // 2) total = text+audio+visual
    int n4 = MM * HH / 4;
    sum3_kernel<<<4096, 256>>>((const float4*)text, (const float4*)audio,
                               (const float4*)visual, (float4*)pTotal, n4);

    // 3) entropy (speaker path)
    entropy_kernel<<<dim3(MM, 3), 128>>>(text, audio, visual);

    // 4) gating GEMMs: G_m = feat_m @ Aw ; T = total @ Wh
    dim3 gemm_grid(HH / BN, MM / BM, 1);      // (4, 128)
    mma_gemm<0><<<gemm_grid, 256>>>(text,   pAw, nullptr, pG,                 MM, HH, HH, 0, 0, 0);
    mma_gemm<0><<<gemm_grid, 256>>>(audio,  pAw, nullptr, pG + (long long)MM * HH, MM, HH, HH, 0, 0, 0);
    mma_gemm<0><<<gemm_grid, 256>>>(visual, pAw, nullptr, pG + 2LL * MM * HH, MM, HH, HH, 0, 0, 0);
    mma_gemm<0><<<gemm_grid, 256>>>(pTotal, pWh, nullptr, pT,                 MM, HH, HH, 0, 0, 0);

    // 5) gate + fuse into h0 [M, 3H]
    gate_fuse_kernel<<<dim3(MM, 3), 128>>>(gate_b, text, audio, visual);

    // 6) normalized adjacency
    degree_kernel<<<dim3(SS, BB), 256>>>(sp, tp);
    normadj_kernel<<<8192, 256>>>(sp, tp);

    // 7) spectral GNN
    dim3 adj_grid(HH / BN, SS / BM, BB);      // (4, 8, 16)
    long long sAdj = (long long)SS * SS, sF = (long long)SS * HH;

    mma_gemm<0><<<gemm_grid, 256>>>(pH0, W0, nullptr, pTmp, MM, HH, H3, 0, 0, 0);
    mma_gemm<1><<<adj_grid, 256>>>(pNadj, pTmp, b0, pH, SS, HH, SS, sAdj, sF, sF);

    mma_gemm<0><<<gemm_grid, 256>>>(pH, W1, nullptr, pTmp, MM, HH, HH, 0, 0, 0);
    mma_gemm<1><<<adj_grid, 256>>>(pNadj, pTmp, b1, pH, SS, HH, SS, sAdj, sF, sF);

    mma_gemm<0><<<gemm_grid, 256>>>(pH, W2, nullptr, pTmp, MM, HH, HH, 0, 0, 0);
    mma_gemm<1><<<adj_grid, 256>>>(pNadj, pTmp, b2, pH, SS, HH, SS, sAdj, sF, sF);

    // 8) classifier
    classifier_kernel<<<MM, 224>>>(bc, out);
}